// round 2
// baseline (speedup 1.0000x reference)
#include <cuda_runtime.h>

// Problem constants
#define BATCH 4
#define SEQ   1024
#define HNUM  16
#define HDIM  64
#define MTOT  4096   // BATCH*SEQ
#define KDIM  1024   // model dim / proj input dim

// Scratch (static device globals; no allocation in kernel_launch)
__device__ float g_k[BATCH*HNUM*SEQ*HDIM];     // [B,H,Lkv,64]
__device__ float g_v[BATCH*HNUM*SEQ*HDIM];     // [B,H,Lkv,64]
__device__ float g_multi[MTOT*KDIM];           // concatenated head outputs [4096,1024]

// ---------------------------------------------------------------------------
// Tiled SGEMM: C[4096, 16*64] = A[4096,1024] @ W + bias, processed in 64-col
// N-tiles. For projections: W tile nt is the dense [1024,64] per-head matrix
// at W + nt*65536 (ldw=64). For the output projection: W tile nt is
// Wo + nt*64 (ldw=1024).
// MODE 0: write row-major [M,1024] to outp.
// MODE 1: write K/V scratch layout [B,H,Lkv,64] (kvsel chooses g_k / g_v).
// ASEL 1: read A from g_multi (final projection).
// ---------------------------------------------------------------------------
template<int MODE, int ASEL>
__global__ __launch_bounds__(256) void gemm64(
    const float* __restrict__ Ain, const float* __restrict__ W,
    const float* __restrict__ bias, float* __restrict__ outp,
    int ldw, int tile_stride, int kvsel)
{
    __shared__ float As[16][64];   // [k][m]
    __shared__ float Bs[16][64];   // [k][n]

    const float* A = ASEL ? g_multi : Ain;
    float* dst = (MODE == 1) ? (kvsel ? g_v : g_k) : outp;

    const int nt = blockIdx.x;       // n-tile (head for projections)
    const int mt = blockIdx.y;
    const int tid = threadIdx.x;
    const int tx = tid & 15, ty = tid >> 4;
    const float* Wt = W + nt * tile_stride;
    const int m0 = mt << 6;

    const int am = tid & 63;            // A row within tile
    const int ak = (tid >> 6) << 2;     // A k-offset (0,4,8,12)
    const int bk = tid >> 4;            // B k-row (0..15)
    const int bn = (tid & 15) << 2;     // B col offset

    float acc[4][4] = {};

    for (int k0 = 0; k0 < KDIM; k0 += 16) {
        float4 av = *(const float4*)(A + (m0 + am) * KDIM + k0 + ak);
        float4 bv = *(const float4*)(Wt + (k0 + bk) * ldw + bn);
        __syncthreads();
        As[ak+0][am] = av.x; As[ak+1][am] = av.y;
        As[ak+2][am] = av.z; As[ak+3][am] = av.w;
        *(float4*)&Bs[bk][bn] = bv;
        __syncthreads();
        #pragma unroll
        for (int k = 0; k < 16; k++) {
            float4 a4 = *(const float4*)&As[k][ty << 2];
            float4 b4 = *(const float4*)&Bs[k][tx << 2];
            float a[4] = {a4.x, a4.y, a4.z, a4.w};
            float b[4] = {b4.x, b4.y, b4.z, b4.w};
            #pragma unroll
            for (int i = 0; i < 4; i++)
                #pragma unroll
                for (int j = 0; j < 4; j++)
                    acc[i][j] = fmaf(a[i], b[j], acc[i][j]);
        }
    }

    float bb[4];
    #pragma unroll
    for (int j = 0; j < 4; j++) bb[j] = bias[(nt << 6) + (tx << 2) + j];

    #pragma unroll
    for (int i = 0; i < 4; i++) {
        int r = m0 + (ty << 2) + i;
        float4 v = make_float4(acc[i][0] + bb[0], acc[i][1] + bb[1],
                               acc[i][2] + bb[2], acc[i][3] + bb[3]);
        if (MODE == 0) {
            *(float4*)(dst + (size_t)r * KDIM + (nt << 6) + (tx << 2)) = v;
        } else {
            int batch = r >> 10, l = r & 1023;
            *(float4*)(dst + (((batch * HNUM + nt) << 16)) + (l << 6) + (tx << 2)) = v;
        }
    }
}

// ---------------------------------------------------------------------------
// Flash attention: one block per (q-tile of 64, bh). Q read from the residual
// region of d_out (residual layout == concatenated-head Q). Online softmax in
// registers; 16-lane shuffle reductions (row r is owned by the 16 tx-lanes of
// warp-half ty). KPs buffer aliased: K^T during QK^T, then P for PV.
// ---------------------------------------------------------------------------
__global__ __launch_bounds__(256) void attn64(const float* __restrict__ Qres)
{
    __shared__ float Qst[64][64];   // [hd][q]  (transposed)
    __shared__ float KPs[64][64];   // K: [hd][kv] transposed; then P: [q][kv]
    __shared__ float Vs[64][64];    // [kv][hd] natural

    const int qt = blockIdx.x;           // 0..15
    const int bh = blockIdx.y;           // 0..63
    const int b = bh >> 4, h = bh & 15;
    const int tid = threadIdx.x;
    const int tx = tid & 15, ty = tid >> 4;
    const int q0 = qt << 6;

    // Load Q tile transposed (64 q-rows x 64 hd) from residual region
    const float* qp = Qres + (size_t)(b * SEQ + q0) * KDIM + (h << 6);
    {
        int r = tid & 63, mc = (tid >> 6) << 4;
        #pragma unroll
        for (int u = 0; u < 4; u++) {
            float4 v = *(const float4*)(qp + r * KDIM + mc + (u << 2));
            Qst[mc + (u << 2) + 0][r] = v.x; Qst[mc + (u << 2) + 1][r] = v.y;
            Qst[mc + (u << 2) + 2][r] = v.z; Qst[mc + (u << 2) + 3][r] = v.w;
        }
    }

    const float* kp = g_k + (size_t)bh * SEQ * HDIM;
    const float* vp = g_v + (size_t)bh * SEQ * HDIM;

    float o[4][4] = {};
    float rmax[4], rsum[4];
    #pragma unroll
    for (int i = 0; i < 4; i++) { rmax[i] = -1e30f; rsum[i] = 0.f; }

    for (int kt = 0; kt < 16; kt++) {
        const float* kt_p = kp + (size_t)(kt << 6) * HDIM;
        const float* vt_p = vp + (size_t)(kt << 6) * HDIM;

        __syncthreads();   // previous iteration's PV reads complete
        {
            // K transposed scatter (conflict-free: lanes have consecutive r)
            int r = tid & 63, mc = (tid >> 6) << 4;
            #pragma unroll
            for (int u = 0; u < 4; u++) {
                float4 v = *(const float4*)(kt_p + r * HDIM + mc + (u << 2));
                KPs[mc + (u << 2) + 0][r] = v.x; KPs[mc + (u << 2) + 1][r] = v.y;
                KPs[mc + (u << 2) + 2][r] = v.z; KPs[mc + (u << 2) + 3][r] = v.w;
            }
            // V linear contiguous copy (tile is contiguous in g_v)
            #pragma unroll
            for (int u = 0; u < 4; u++) {
                int flat = (u << 10) + (tid << 2);
                *(float4*)(&Vs[0][0] + flat) = *(const float4*)(vt_p + flat);
            }
        }
        __syncthreads();

        // S = (Q K^T) * scale ; thread owns rows 4ty+i, cols 4tx+j
        float s[4][4] = {};
        #pragma unroll 8
        for (int m = 0; m < 64; m++) {
            float4 a4 = *(const float4*)&Qst[m][ty << 2];
            float4 b4 = *(const float4*)&KPs[m][tx << 2];
            float a[4] = {a4.x, a4.y, a4.z, a4.w};
            float bv[4] = {b4.x, b4.y, b4.z, b4.w};
            #pragma unroll
            for (int i = 0; i < 4; i++)
                #pragma unroll
                for (int j = 0; j < 4; j++)
                    s[i][j] = fmaf(a[i], bv[j], s[i][j]);
        }

        // online softmax in registers (per row, reduced over 16 tx lanes)
        #pragma unroll
        for (int i = 0; i < 4; i++) {
            float tm = -1e30f;
            #pragma unroll
            for (int j = 0; j < 4; j++) { s[i][j] *= 0.125f; tm = fmaxf(tm, s[i][j]); }
            #pragma unroll
            for (int off = 1; off < 16; off <<= 1)
                tm = fmaxf(tm, __shfl_xor_sync(0xffffffffu, tm, off));
            float nm = fmaxf(rmax[i], tm);
            float cf = __expf(rmax[i] - nm);
            rmax[i] = nm;
            float ls = 0.f;
            #pragma unroll
            for (int j = 0; j < 4; j++) { s[i][j] = __expf(s[i][j] - nm); ls += s[i][j]; }
            #pragma unroll
            for (int off = 1; off < 16; off <<= 1)
                ls += __shfl_xor_sync(0xffffffffu, ls, off);
            rsum[i] = rsum[i] * cf + ls;
            #pragma unroll
            for (int j = 0; j < 4; j++) o[i][j] *= cf;
        }

        __syncthreads();   // everyone done reading KPs as K^T
        #pragma unroll
        for (int i = 0; i < 4; i++)
            *(float4*)&KPs[(ty << 2) + i][tx << 2] =
                make_float4(s[i][0], s[i][1], s[i][2], s[i][3]);
        __syncthreads();

        // O += P @ V
        #pragma unroll 8
        for (int kc = 0; kc < 64; kc++) {
            float4 b4 = *(const float4*)&Vs[kc][tx << 2];
            float bv[4] = {b4.x, b4.y, b4.z, b4.w};
            #pragma unroll
            for (int i = 0; i < 4; i++) {
                float a = KPs[(ty << 2) + i][kc];
                #pragma unroll
                for (int j = 0; j < 4; j++)
                    o[i][j] = fmaf(a, bv[j], o[i][j]);
            }
        }
    }

    // normalize and write to multi buffer (concatenated head layout)
    #pragma unroll
    for (int i = 0; i < 4; i++) {
        float inv = 1.0f / rsum[i];
        int r = b * SEQ + q0 + (ty << 2) + i;
        *(float4*)(g_multi + (size_t)r * KDIM + (h << 6) + (tx << 2)) =
            make_float4(o[i][0] * inv, o[i][1] * inv, o[i][2] * inv, o[i][3] * inv);
    }
}

// ---------------------------------------------------------------------------
extern "C" void kernel_launch(void* const* d_in, const int* in_sizes, int n_in,
                              void* d_out, int out_size)
{
    const float* queries = (const float*)d_in[0];
    const float* context = (const float*)d_in[1];
    const float* Wq = (const float*)d_in[2];
    const float* bq = (const float*)d_in[3];
    const float* Wk = (const float*)d_in[4];
    const float* bk = (const float*)d_in[5];
    const float* Wv = (const float*)d_in[6];
    const float* bv = (const float*)d_in[7];
    const float* Wo = (const float*)d_in[8];
    const float* bo = (const float*)d_in[9];

    float* out = (float*)d_out;                     // [4096,1024] final out
    float* res = out + (size_t)MTOT * KDIM;         // [4096,1024] residual (= Q concat)

    dim3 grid(16, 64);

    // Q projection -> residual region (also serves as Q for attention)
    gemm64<0,0><<<grid, 256>>>(queries, Wq, bq, res, HDIM, KDIM*HDIM, 0);
    // K projection -> g_k, V projection -> g_v
    gemm64<1,0><<<grid, 256>>>(context, Wk, bk, nullptr, HDIM, KDIM*HDIM, 0);
    gemm64<1,0><<<grid, 256>>>(context, Wv, bv, nullptr, HDIM, KDIM*HDIM, 1);
    // Attention -> g_multi
    attn64<<<dim3(16, 64), 256>>>(res);
    // Output projection -> out
    gemm64<0,1><<<grid, 256>>>(nullptr, Wo, bo, out, KDIM, HDIM, 0);
}

// round 3
// speedup vs baseline: 2.5054x; 2.5054x over previous
#include <cuda_runtime.h>

#define BATCH 4
#define SEQ   1024
#define HNUM  16
#define HDIM  64
#define MTOT  4096
#define KDIM  1024

__device__ float g_k[BATCH*HNUM*SEQ*HDIM];     // [B,H,Lkv,64]
__device__ float g_v[BATCH*HNUM*SEQ*HDIM];     // [B,H,Lkv,64]
__device__ float g_multi[MTOT*KDIM];           // concat head outputs [4096,1024]

__device__ __forceinline__ unsigned f2tf(float x){
    unsigned r; asm("cvt.rna.tf32.f32 %0, %1;" : "=r"(r) : "f"(x)); return r;
}
__device__ __forceinline__ void mma8(float* c, const unsigned* a, const unsigned* b){
    asm volatile("mma.sync.aligned.m16n8k8.row.col.f32.tf32.tf32.f32 "
        "{%0,%1,%2,%3}, {%4,%5,%6,%7}, {%8,%9}, {%0,%1,%2,%3};"
        : "+f"(c[0]),"+f"(c[1]),"+f"(c[2]),"+f"(c[3])
        : "r"(a[0]),"r"(a[1]),"r"(a[2]),"r"(a[3]),"r"(b[0]),"r"(b[1]));
}

// ---------------------------------------------------------------------------
// tf32 tensor-core GEMM: C[4096, nt*64..] = A[4096,1024] @ Wtile[1024,64] + b
// Block tile 128x64, 8 warps (4x2) of 32x32 warp tiles, BK=32.
// MODE 0: row-major [M,1024] out. MODE 1: K/V scratch [B,H,L,64].
// ASEL 1: A = g_multi.
// ---------------------------------------------------------------------------
template<int MODE,int ASEL>
__global__ __launch_bounds__(256) void gemm_tf32(
    const float* __restrict__ Ain, const float* __restrict__ W,
    const float* __restrict__ bias, float* __restrict__ outp,
    int ldw, int tile_stride, int kvsel)
{
    __shared__ unsigned As[128][36];   // [m][k], stride%32==4 -> conflict-free frags
    __shared__ unsigned Bs[32][72];    // [k][n], stride%32==8 -> conflict-free frags

    const float* A = ASEL ? g_multi : Ain;
    float* dst = (MODE==1) ? (kvsel ? g_v : g_k) : outp;

    const int nt = blockIdx.x, mt = blockIdx.y;
    const int tid = threadIdx.x;
    const int lane = tid & 31, warp = tid >> 5;
    const int wm = warp & 3, wn = warp >> 2;
    const int lr = lane >> 2, lc = lane & 3;
    const int m0 = mt << 7;
    const float* Wt = W + (size_t)nt * tile_stride;

    float acc[2][4][4] = {};

    for (int k0 = 0; k0 < KDIM; k0 += 32) {
        __syncthreads();
        #pragma unroll
        for (int i = 0; i < 4; i++) {
            int s = tid + (i << 8);
            int row = s >> 3, c4 = (s & 7) << 2;
            float4 v = *(const float4*)(A + (size_t)(m0 + row)*KDIM + k0 + c4);
            As[row][c4]   = f2tf(v.x); As[row][c4+1] = f2tf(v.y);
            As[row][c4+2] = f2tf(v.z); As[row][c4+3] = f2tf(v.w);
        }
        #pragma unroll
        for (int i = 0; i < 2; i++) {
            int s = tid + (i << 8);
            int row = s >> 4, c4 = (s & 15) << 2;
            float4 v = *(const float4*)(Wt + (size_t)(k0 + row)*ldw + c4);
            Bs[row][c4]   = f2tf(v.x); Bs[row][c4+1] = f2tf(v.y);
            Bs[row][c4+2] = f2tf(v.z); Bs[row][c4+3] = f2tf(v.w);
        }
        __syncthreads();
        #pragma unroll
        for (int kk = 0; kk < 4; kk++) {
            unsigned a[2][4], bfr[4][2];
            #pragma unroll
            for (int mi = 0; mi < 2; mi++) {
                int rb = wm*32 + mi*16 + lr;
                int cb = kk*8 + lc;
                a[mi][0] = As[rb][cb];   a[mi][1] = As[rb+8][cb];
                a[mi][2] = As[rb][cb+4]; a[mi][3] = As[rb+8][cb+4];
            }
            #pragma unroll
            for (int nf = 0; nf < 4; nf++) {
                int nn = wn*32 + nf*8 + lr;
                bfr[nf][0] = Bs[kk*8 + lc][nn];
                bfr[nf][1] = Bs[kk*8 + lc + 4][nn];
            }
            #pragma unroll
            for (int mi = 0; mi < 2; mi++)
                #pragma unroll
                for (int nf = 0; nf < 4; nf++)
                    mma8(acc[mi][nf], a[mi], bfr[nf]);
        }
    }

    const float* bp = bias + (nt << 6);
    #pragma unroll
    for (int mi = 0; mi < 2; mi++) {
        #pragma unroll
        for (int nf = 0; nf < 4; nf++) {
            int cb = wn*32 + nf*8 + 2*lc;
            float b0 = bp[cb], b1 = bp[cb+1];
            int r1 = m0 + wm*32 + mi*16 + lr;
            int r2 = r1 + 8;
            float2 v1 = make_float2(acc[mi][nf][0]+b0, acc[mi][nf][1]+b1);
            float2 v2 = make_float2(acc[mi][nf][2]+b0, acc[mi][nf][3]+b1);
            if (MODE == 0) {
                *(float2*)(dst + (size_t)r1*KDIM + (nt<<6) + cb) = v1;
                *(float2*)(dst + (size_t)r2*KDIM + (nt<<6) + cb) = v2;
            } else {
                int ba = r1 >> 10, l = r1 & 1023;
                *(float2*)(dst + ((size_t)(ba*HNUM + nt)<<16) + (l<<6) + cb) = v1;
                ba = r2 >> 10; l = r2 & 1023;
                *(float2*)(dst + ((size_t)(ba*HNUM + nt)<<16) + (l<<6) + cb) = v2;
            }
        }
    }
}

// ---------------------------------------------------------------------------
// tf32 flash attention. Block = (64-query tile, bh). 8 warps (4x2), warp tile
// 16x32 for both S=QK^T and O=PV. Q fragments cached in registers for the
// whole kv loop. KS buffer aliased: K^T operand, then P (softmaxed scores).
// ---------------------------------------------------------------------------
__global__ __launch_bounds__(256) void attn_tf32(const float* __restrict__ Qres)
{
    __shared__ unsigned KS[64][68];   // stride%32==4 -> conflict-free frags
    __shared__ unsigned Vs[64][68];
    __shared__ float rmax_s[64], rsum_s[64], rcf_s[64];

    const int qt = blockIdx.x, bh = blockIdx.y;
    const int bb = bh >> 4, h = bh & 15;
    const int tid = threadIdx.x;
    const int lane = tid & 31, warp = tid >> 5;
    const int wq = warp & 3, wn = warp >> 2;
    const int lr = lane >> 2, lc = lane & 3;
    const int q0 = qt << 6;

    // Q tile -> smem -> register fragments (held for entire kv loop)
    const float* qp = Qres + (size_t)(bb*SEQ + q0)*KDIM + (h<<6);
    #pragma unroll
    for (int i = 0; i < 4; i++) {
        int s = tid + (i<<8);
        int row = s >> 4, c4 = (s & 15) << 2;
        float4 v = *(const float4*)(qp + (size_t)row*KDIM + c4);
        KS[row][c4]   = f2tf(v.x); KS[row][c4+1] = f2tf(v.y);
        KS[row][c4+2] = f2tf(v.z); KS[row][c4+3] = f2tf(v.w);
    }
    if (tid < 64) { rmax_s[tid] = -1e30f; rsum_s[tid] = 0.f; }
    __syncthreads();

    unsigned Qa[8][4];
    #pragma unroll
    for (int kk = 0; kk < 8; kk++) {
        int rb = wq*16 + lr, cb = kk*8 + lc;
        Qa[kk][0] = KS[rb][cb];   Qa[kk][1] = KS[rb+8][cb];
        Qa[kk][2] = KS[rb][cb+4]; Qa[kk][3] = KS[rb+8][cb+4];
    }

    const float* kp = g_k + (size_t)bh*SEQ*HDIM;
    const float* vp = g_v + (size_t)bh*SEQ*HDIM;

    float o[4][4] = {};

    for (int kt = 0; kt < 16; kt++) {
        __syncthreads();   // Qa filled / previous PV reads done
        const float* ktp = kp + (size_t)(kt<<6)*HDIM;
        const float* vtp = vp + (size_t)(kt<<6)*HDIM;
        #pragma unroll
        for (int i = 0; i < 4; i++) {
            int s = tid + (i<<8);
            int row = s >> 4, c4 = (s & 15) << 2;
            float4 kv4 = *(const float4*)(ktp + row*HDIM + c4);
            float4 vv4 = *(const float4*)(vtp + row*HDIM + c4);
            KS[row][c4]=f2tf(kv4.x); KS[row][c4+1]=f2tf(kv4.y);
            KS[row][c4+2]=f2tf(kv4.z); KS[row][c4+3]=f2tf(kv4.w);
            Vs[row][c4]=f2tf(vv4.x); Vs[row][c4+1]=f2tf(vv4.y);
            Vs[row][c4+2]=f2tf(vv4.z); Vs[row][c4+3]=f2tf(vv4.w);
        }
        __syncthreads();

        // S = Q @ K^T
        float sc[4][4] = {};
        #pragma unroll
        for (int kk = 0; kk < 8; kk++) {
            unsigned bfr[4][2];
            #pragma unroll
            for (int nf = 0; nf < 4; nf++) {
                int nn = wn*32 + nf*8 + lr;
                bfr[nf][0] = KS[nn][kk*8 + lc];
                bfr[nf][1] = KS[nn][kk*8 + lc + 4];
            }
            #pragma unroll
            for (int nf = 0; nf < 4; nf++)
                mma8(sc[nf], Qa[kk], bfr[nf]);
        }
        __syncthreads();   // everyone done reading KS as K

        // write scaled scores into KS (now the P buffer), raw fp32
        #pragma unroll
        for (int nf = 0; nf < 4; nf++) {
            int cb = wn*32 + nf*8 + 2*lc;
            int r1 = wq*16 + lr;
            float2 v1 = make_float2(sc[nf][0]*0.125f, sc[nf][1]*0.125f);
            float2 v2 = make_float2(sc[nf][2]*0.125f, sc[nf][3]*0.125f);
            *(float2*)&KS[r1][cb]   = v1;
            *(float2*)&KS[r1+8][cb] = v2;
        }
        __syncthreads();

        // online softmax: 4 lanes own one row (16 cols each)
        {
            int r = tid >> 2, seg = tid & 3;
            float v[16];
            *(float4*)&v[0]  = *(float4*)&KS[r][seg*16];
            *(float4*)&v[4]  = *(float4*)&KS[r][seg*16+4];
            *(float4*)&v[8]  = *(float4*)&KS[r][seg*16+8];
            *(float4*)&v[12] = *(float4*)&KS[r][seg*16+12];
            float tm = -1e30f;
            #pragma unroll
            for (int j = 0; j < 16; j++) tm = fmaxf(tm, v[j]);
            tm = fmaxf(tm, __shfl_xor_sync(0xffffffffu, tm, 1));
            tm = fmaxf(tm, __shfl_xor_sync(0xffffffffu, tm, 2));
            float old = rmax_s[r];
            float nm = fmaxf(old, tm);
            float ls = 0.f;
            #pragma unroll
            for (int j = 0; j < 16; j++) { v[j] = __expf(v[j]-nm); ls += v[j]; }
            ls += __shfl_xor_sync(0xffffffffu, ls, 1);
            ls += __shfl_xor_sync(0xffffffffu, ls, 2);
            uint4 pk;
            #pragma unroll
            for (int g = 0; g < 4; g++) {
                pk.x = f2tf(v[g*4]);   pk.y = f2tf(v[g*4+1]);
                pk.z = f2tf(v[g*4+2]); pk.w = f2tf(v[g*4+3]);
                *(uint4*)&KS[r][seg*16 + g*4] = pk;
            }
            if (seg == 0) {
                float cf = __expf(old - nm);
                rcf_s[r]  = cf;
                rsum_s[r] = rsum_s[r]*cf + ls;
                rmax_s[r] = nm;
            }
        }
        __syncthreads();

        // rescale O accumulators
        {
            float cf1 = rcf_s[wq*16 + lr], cf2 = rcf_s[wq*16 + lr + 8];
            #pragma unroll
            for (int nf = 0; nf < 4; nf++) {
                o[nf][0] *= cf1; o[nf][1] *= cf1;
                o[nf][2] *= cf2; o[nf][3] *= cf2;
            }
        }

        // O += P @ V
        #pragma unroll
        for (int kk = 0; kk < 8; kk++) {
            unsigned a[4];
            int rb = wq*16 + lr, cb = kk*8 + lc;
            a[0] = KS[rb][cb];   a[1] = KS[rb+8][cb];
            a[2] = KS[rb][cb+4]; a[3] = KS[rb+8][cb+4];
            unsigned bfr[4][2];
            #pragma unroll
            for (int nf = 0; nf < 4; nf++) {
                int nn = wn*32 + nf*8 + lr;
                bfr[nf][0] = Vs[cb][nn];
                bfr[nf][1] = Vs[cb+4][nn];
            }
            #pragma unroll
            for (int nf = 0; nf < 4; nf++)
                mma8(o[nf], a, bfr[nf]);
        }
    }

    // normalize and write concat-head output
    float inv1 = 1.f / rsum_s[wq*16 + lr];
    float inv2 = 1.f / rsum_s[wq*16 + lr + 8];
    #pragma unroll
    for (int nf = 0; nf < 4; nf++) {
        int cb = wn*32 + nf*8 + 2*lc;
        int r1 = bb*SEQ + q0 + wq*16 + lr;
        int r2 = r1 + 8;
        *(float2*)(g_multi + (size_t)r1*KDIM + (h<<6) + cb) =
            make_float2(o[nf][0]*inv1, o[nf][1]*inv1);
        *(float2*)(g_multi + (size_t)r2*KDIM + (h<<6) + cb) =
            make_float2(o[nf][2]*inv2, o[nf][3]*inv2);
    }
}

// ---------------------------------------------------------------------------
extern "C" void kernel_launch(void* const* d_in, const int* in_sizes, int n_in,
                              void* d_out, int out_size)
{
    const float* queries = (const float*)d_in[0];
    const float* context = (const float*)d_in[1];
    const float* Wq = (const float*)d_in[2];
    const float* bq = (const float*)d_in[3];
    const float* Wk = (const float*)d_in[4];
    const float* bk = (const float*)d_in[5];
    const float* Wv = (const float*)d_in[6];
    const float* bv = (const float*)d_in[7];
    const float* Wo = (const float*)d_in[8];
    const float* bo = (const float*)d_in[9];

    float* out = (float*)d_out;
    float* res = out + (size_t)MTOT * KDIM;

    dim3 gp(16, 32);
    gemm_tf32<0,0><<<gp,256>>>(queries, Wq, bq, res, HDIM, KDIM*HDIM, 0);
    gemm_tf32<1,0><<<gp,256>>>(context, Wk, bk, nullptr, HDIM, KDIM*HDIM, 0);
    gemm_tf32<1,0><<<gp,256>>>(context, Wv, bv, nullptr, HDIM, KDIM*HDIM, 1);
    attn_tf32<<<dim3(16,64),256>>>(res);
    gemm_tf32<0,1><<<gp,256>>>(nullptr, Wo, bo, out, KDIM, 64, 0);
}

// round 4
// speedup vs baseline: 3.8125x; 1.5217x over previous
#include <cuda_runtime.h>

#define BATCH 4
#define SEQ   1024
#define HNUM  16
#define HDIM  64
#define MTOT  4096
#define KDIM  1024

// Scratch (tf32-bit patterns stored as unsigned)
__device__ unsigned g_qt[MTOT*KDIM];
__device__ unsigned g_ct[MTOT*KDIM];
__device__ unsigned g_wq[HNUM*KDIM*HDIM];
__device__ unsigned g_wk[HNUM*KDIM*HDIM];
__device__ unsigned g_wv[HNUM*KDIM*HDIM];
__device__ unsigned g_wo[KDIM*KDIM];
__device__ unsigned g_k[BATCH*HNUM*SEQ*HDIM];   // [B,H,Lkv,64] tf32 bits
__device__ unsigned g_v[BATCH*HNUM*SEQ*HDIM];
__device__ unsigned g_multi[MTOT*KDIM];         // concat head outputs, tf32 bits

__device__ __forceinline__ unsigned f2tf(float x){
    unsigned r; asm("cvt.rna.tf32.f32 %0, %1;" : "=r"(r) : "f"(x)); return r;
}
__device__ __forceinline__ float ex2(float x){
    float r; asm("ex2.approx.ftz.f32 %0, %1;" : "=f"(r) : "f"(x)); return r;
}
__device__ __forceinline__ void mma8(float* c, const unsigned* a, const unsigned* b){
    asm volatile("mma.sync.aligned.m16n8k8.row.col.f32.tf32.tf32.f32 "
        "{%0,%1,%2,%3}, {%4,%5,%6,%7}, {%8,%9}, {%0,%1,%2,%3};"
        : "+f"(c[0]),"+f"(c[1]),"+f"(c[2]),"+f"(c[3])
        : "r"(a[0]),"r"(a[1]),"r"(a[2]),"r"(a[3]),"r"(b[0]),"r"(b[1]));
}
__device__ __forceinline__ void cpa16(unsigned dst, const void* src){
    asm volatile("cp.async.cg.shared.global [%0], [%1], 16;" :: "r"(dst), "l"(src));
}
#define CP_COMMIT asm volatile("cp.async.commit_group;")
#define CP_WAIT1  asm volatile("cp.async.wait_group 1;")
#define CP_WAIT0  asm volatile("cp.async.wait_group 0;")

// ---------------------------------------------------------------------------
// Pre-pass: round inputs + all weights to tf32 once. 12M elements.
// ---------------------------------------------------------------------------
__global__ __launch_bounds__(256) void cvt_pre(
    const float* __restrict__ q, const float* __restrict__ c,
    const float* __restrict__ wq, const float* __restrict__ wk,
    const float* __restrict__ wv, const float* __restrict__ wo)
{
    int i = blockIdx.x * 256 + threadIdx.x;   // float4 index, total 3145728
    const float* s; unsigned* d; int off;
    if      (i < 1048576) { s = q;  d = g_qt; off = i; }
    else if (i < 2097152) { s = c;  d = g_ct; off = i - 1048576; }
    else if (i < 2359296) { s = wq; d = g_wq; off = i - 2097152; }
    else if (i < 2621440) { s = wk; d = g_wk; off = i - 2359296; }
    else if (i < 2883584) { s = wv; d = g_wv; off = i - 2621440; }
    else                  { s = wo; d = g_wo; off = i - 2883584; }
    float4 v = ((const float4*)s)[off];
    uint4 u = make_uint4(f2tf(v.x), f2tf(v.y), f2tf(v.z), f2tf(v.w));
    ((uint4*)d)[off] = u;
}

// ---------------------------------------------------------------------------
// tf32 GEMM, cp.async double-buffered. Block 128x64, BK=32, 8 warps (4x2).
// Operands pre-rounded -> no cvt in the loop.
// MODE 0: float out [M,1024] (+bias exact). MODE 1: tf32-rounded KV scratch,
// grid.x=32 selects K (W0) vs V (W1).
// ---------------------------------------------------------------------------
template<int MODE>
__global__ __launch_bounds__(256,2) void gemm_tc(
    const unsigned* __restrict__ A,
    const unsigned* __restrict__ W0, const unsigned* __restrict__ W1,
    const float* __restrict__ bias0, const float* __restrict__ bias1,
    void* out0, void* out1, int ldw, int tstride)
{
    extern __shared__ unsigned sh[];
    unsigned* As = sh;               // [2][128][36]
    unsigned* Bs = sh + 2*128*36;    // [2][32][72]
    const unsigned sb  = (unsigned)__cvta_generic_to_shared(sh);
    const unsigned sbB = sb + 2*128*36*4;

    const int sel = (MODE==1) ? (blockIdx.x >> 4) : 0;
    const int nt  = (MODE==1) ? (blockIdx.x & 15) : blockIdx.x;
    const unsigned* W = sel ? W1 : W0;
    const float* bias = sel ? bias1 : bias0;

    const int tid = threadIdx.x;
    const int lane = tid & 31, warp = tid >> 5;
    const int wm = warp & 3, wn = warp >> 2;
    const int lr = lane >> 2, lc = lane & 3;
    const int m0 = blockIdx.y << 7;
    const unsigned* Wt = W + (size_t)nt * tstride;

    const int arow = tid >> 3, ac4 = (tid & 7) << 2;
    const int brow = tid >> 4, bc4 = (tid & 15) << 2;

    float acc[2][4][4] = {};

    // prefetch tile 0
    {
        unsigned ad = sb + (unsigned)((arow*36 + ac4)*4);
        const unsigned* asrc = A + (size_t)(m0+arow)*KDIM + ac4;
        #pragma unroll
        for (int i=0;i<4;i++) cpa16(ad + i*32*36*4, asrc + (size_t)i*32*KDIM);
        unsigned bd = sbB + (unsigned)((brow*72 + bc4)*4);
        const unsigned* bsrc = Wt + (size_t)brow*ldw + bc4;
        #pragma unroll
        for (int i=0;i<2;i++) cpa16(bd + i*16*72*4, bsrc + (size_t)i*16*ldw);
        CP_COMMIT;
    }

    for (int it = 0; it < 32; it++) {
        __syncthreads();                       // all warps done with other buffer
        if (it < 31) {
            int k0 = (it+1) << 5, buf = (it+1) & 1;
            unsigned ad = sb + (unsigned)((buf*128*36 + arow*36 + ac4)*4);
            const unsigned* asrc = A + (size_t)(m0+arow)*KDIM + k0 + ac4;
            #pragma unroll
            for (int i=0;i<4;i++) cpa16(ad + i*32*36*4, asrc + (size_t)i*32*KDIM);
            unsigned bd = sbB + (unsigned)((buf*32*72 + brow*72 + bc4)*4);
            const unsigned* bsrc = Wt + (size_t)(k0+brow)*ldw + bc4;
            #pragma unroll
            for (int i=0;i<2;i++) cpa16(bd + i*16*72*4, bsrc + (size_t)i*16*ldw);
            CP_COMMIT;
            CP_WAIT1;
        } else {
            CP_WAIT0;
        }
        __syncthreads();                       // tile it visible to all

        const unsigned* Ab = As + (it&1)*128*36;
        const unsigned* Bb = Bs + (it&1)*32*72;
        #pragma unroll
        for (int kk = 0; kk < 4; kk++) {
            unsigned a[2][4], b[4][2];
            #pragma unroll
            for (int mi = 0; mi < 2; mi++) {
                int rb = wm*32 + mi*16 + lr, cb = kk*8 + lc;
                a[mi][0] = Ab[rb*36+cb];     a[mi][1] = Ab[(rb+8)*36+cb];
                a[mi][2] = Ab[rb*36+cb+4];   a[mi][3] = Ab[(rb+8)*36+cb+4];
            }
            #pragma unroll
            for (int nf = 0; nf < 4; nf++) {
                int nn = wn*32 + nf*8 + lr;
                b[nf][0] = Bb[(kk*8+lc)*72+nn];
                b[nf][1] = Bb[(kk*8+lc+4)*72+nn];
            }
            #pragma unroll
            for (int mi = 0; mi < 2; mi++)
                #pragma unroll
                for (int nf = 0; nf < 4; nf++)
                    mma8(acc[mi][nf], a[mi], b[nf]);
        }
    }

    const float* bp = bias + (nt << 6);
    #pragma unroll
    for (int mi = 0; mi < 2; mi++) {
        #pragma unroll
        for (int nf = 0; nf < 4; nf++) {
            int cb = wn*32 + nf*8 + 2*lc;
            float b0 = bp[cb], b1 = bp[cb+1];
            int r1 = m0 + wm*32 + mi*16 + lr;
            int r2 = r1 + 8;
            if (MODE == 0) {
                float* dst = (float*)out0;
                *(float2*)(dst + (size_t)r1*KDIM + (nt<<6) + cb) =
                    make_float2(acc[mi][nf][0]+b0, acc[mi][nf][1]+b1);
                *(float2*)(dst + (size_t)r2*KDIM + (nt<<6) + cb) =
                    make_float2(acc[mi][nf][2]+b0, acc[mi][nf][3]+b1);
            } else {
                unsigned* dst = (unsigned*)(sel ? out1 : out0);
                int ba = r1 >> 10, l = r1 & 1023;
                *(uint2*)(dst + ((size_t)(ba*HNUM + nt)<<16) + (l<<6) + cb) =
                    make_uint2(f2tf(acc[mi][nf][0]+b0), f2tf(acc[mi][nf][1]+b1));
                ba = r2 >> 10; l = r2 & 1023;
                *(uint2*)(dst + ((size_t)(ba*HNUM + nt)<<16) + (l<<6) + cb) =
                    make_uint2(f2tf(acc[mi][nf][2]+b0), f2tf(acc[mi][nf][3]+b1));
            }
        }
    }
}

// ---------------------------------------------------------------------------
// Per-warp flash attention, cp.async double-buffered K/V, permuted-V PV mma.
// Block: 8 warps x 16 q-rows = 128 q rows of one (b,h). kv tile = 64.
// Softmax entirely in registers (quad shuffles). exp2 domain.
// ---------------------------------------------------------------------------
__global__ __launch_bounds__(256,2) void attn_tc(const float* __restrict__ Qres)
{
    extern __shared__ unsigned sh[];
    const unsigned sb = (unsigned)__cvta_generic_to_shared(sh);
    // Kb: [2][64][68], Vb: [2][64][68]
    unsigned* Kb = sh;
    unsigned* Vb = sh + 2*64*68;
    const unsigned sbV = sb + 2*64*68*4;

    const int qb = blockIdx.x;           // 0..7
    const int bh = blockIdx.y;           // 0..63
    const int bb = bh >> 4, h = bh & 15;
    const int tid = threadIdx.x;
    const int lane = tid & 31, warp = tid >> 5;
    const int lr = lane >> 2, lc = lane & 3;

    // Q fragments, held for the whole loop; fold scale*log2(e) in
    const float SC = 0.125f * 1.44269504f;
    const float* qp = Qres + (size_t)(bb*SEQ + qb*128 + warp*16)*KDIM + (h<<6);
    unsigned Qa[8][4];
    #pragma unroll
    for (int kk = 0; kk < 8; kk++) {
        Qa[kk][0] = f2tf(SC * qp[(size_t)lr*KDIM     + kk*8 + lc]);
        Qa[kk][1] = f2tf(SC * qp[(size_t)(lr+8)*KDIM + kk*8 + lc]);
        Qa[kk][2] = f2tf(SC * qp[(size_t)lr*KDIM     + kk*8 + lc + 4]);
        Qa[kk][3] = f2tf(SC * qp[(size_t)(lr+8)*KDIM + kk*8 + lc + 4]);
    }

    const unsigned* kp = g_k + (size_t)bh*SEQ*HDIM;
    const unsigned* vp = g_v + (size_t)bh*SEQ*HDIM;
    const int krow = tid >> 4, kc4 = (tid & 15) << 2;

    // prefetch tile 0
    {
        #pragma unroll
        for (int i = 0; i < 4; i++) {
            int r = krow + i*16;
            cpa16(sb  + (unsigned)((r*68 + kc4)*4), kp + r*64 + kc4);
            cpa16(sbV + (unsigned)((r*68 + kc4)*4), vp + r*64 + kc4);
        }
        CP_COMMIT;
    }

    float o[8][4] = {};
    float rm1 = -1e30f, rm2 = -1e30f, rl1 = 0.f, rl2 = 0.f;

    for (int kt = 0; kt < 16; kt++) {
        __syncthreads();                 // other buffer free for overwrite
        if (kt < 15) {
            int buf = (kt+1) & 1;
            const unsigned* ks = kp + (size_t)(kt+1)*4096;
            const unsigned* vs = vp + (size_t)(kt+1)*4096;
            #pragma unroll
            for (int i = 0; i < 4; i++) {
                int r = krow + i*16;
                cpa16(sb  + (unsigned)(((buf*64 + r)*68 + kc4)*4), ks + r*64 + kc4);
                cpa16(sbV + (unsigned)(((buf*64 + r)*68 + kc4)*4), vs + r*64 + kc4);
            }
            CP_COMMIT;
            CP_WAIT1;
        } else {
            CP_WAIT0;
        }
        __syncthreads();                 // tile kt visible

        const unsigned* K = Kb + (kt&1)*64*68;
        const unsigned* V = Vb + (kt&1)*64*68;

        // S = Q @ K^T (already in log2 domain via SC)
        float scf[8][4] = {};
        #pragma unroll
        for (int kk = 0; kk < 8; kk++) {
            #pragma unroll
            for (int nf = 0; nf < 8; nf++) {
                unsigned b[2];
                b[0] = K[(nf*8+lr)*68 + kk*8 + lc];
                b[1] = K[(nf*8+lr)*68 + kk*8 + lc + 4];
                mma8(scf[nf], Qa[kk], b);
            }
        }

        // register softmax (rows lr / lr+8, quad = 4 lc lanes)
        float m1 = -1e30f, m2 = -1e30f;
        #pragma unroll
        for (int nf = 0; nf < 8; nf++) {
            m1 = fmaxf(m1, fmaxf(scf[nf][0], scf[nf][1]));
            m2 = fmaxf(m2, fmaxf(scf[nf][2], scf[nf][3]));
        }
        m1 = fmaxf(m1, __shfl_xor_sync(0xffffffffu, m1, 1));
        m1 = fmaxf(m1, __shfl_xor_sync(0xffffffffu, m1, 2));
        m2 = fmaxf(m2, __shfl_xor_sync(0xffffffffu, m2, 1));
        m2 = fmaxf(m2, __shfl_xor_sync(0xffffffffu, m2, 2));
        float nm1 = fmaxf(rm1, m1), nm2 = fmaxf(rm2, m2);
        float cf1 = ex2(rm1 - nm1), cf2 = ex2(rm2 - nm2);
        rm1 = nm1; rm2 = nm2;

        float ls1 = 0.f, ls2 = 0.f;
        unsigned pa[8][4];
        #pragma unroll
        for (int nf = 0; nf < 8; nf++) {
            float p0 = ex2(scf[nf][0] - nm1); ls1 += p0;
            float p1 = ex2(scf[nf][1] - nm1); ls1 += p1;
            float p2 = ex2(scf[nf][2] - nm2); ls2 += p2;
            float p3 = ex2(scf[nf][3] - nm2); ls2 += p3;
            pa[nf][0] = f2tf(p0); pa[nf][1] = f2tf(p1);
            pa[nf][2] = f2tf(p2); pa[nf][3] = f2tf(p3);
        }
        ls1 += __shfl_xor_sync(0xffffffffu, ls1, 1);
        ls1 += __shfl_xor_sync(0xffffffffu, ls1, 2);
        ls2 += __shfl_xor_sync(0xffffffffu, ls2, 1);
        ls2 += __shfl_xor_sync(0xffffffffu, ls2, 2);
        rl1 = rl1*cf1 + ls1;
        rl2 = rl2*cf2 + ls2;

        #pragma unroll
        for (int nf = 0; nf < 8; nf++) {
            o[nf][0] *= cf1; o[nf][1] *= cf1;
            o[nf][2] *= cf2; o[nf][3] *= cf2;
        }

        // O += P @ V with permuted kv index (pi(j) = j<4 ? 2j : 2(j-4)+1):
        // A-frag = {c0, c2, c1, c3} in place; V rows read permuted.
        #pragma unroll
        for (int kc = 0; kc < 8; kc++) {
            unsigned a[4] = { pa[kc][0], pa[kc][2], pa[kc][1], pa[kc][3] };
            #pragma unroll
            for (int nf = 0; nf < 8; nf++) {
                unsigned b[2];
                b[0] = V[(kc*8 + 2*lc    )*68 + nf*8 + lr];
                b[1] = V[(kc*8 + 2*lc + 1)*68 + nf*8 + lr];
                mma8(o[nf], a, b);
            }
        }
    }

    // normalize + store (tf32-rounded for the out-projection)
    float inv1 = 1.f / rl1, inv2 = 1.f / rl2;
    int r1 = bb*SEQ + qb*128 + warp*16 + lr;
    int r2 = r1 + 8;
    #pragma unroll
    for (int nf = 0; nf < 8; nf++) {
        int col = (h<<6) + nf*8 + 2*lc;
        *(uint2*)(g_multi + (size_t)r1*KDIM + col) =
            make_uint2(f2tf(o[nf][0]*inv1), f2tf(o[nf][1]*inv1));
        *(uint2*)(g_multi + (size_t)r2*KDIM + col) =
            make_uint2(f2tf(o[nf][2]*inv2), f2tf(o[nf][3]*inv2));
    }
}

// ---------------------------------------------------------------------------
extern "C" void kernel_launch(void* const* d_in, const int* in_sizes, int n_in,
                              void* d_out, int out_size)
{
    const float* queries = (const float*)d_in[0];
    const float* context = (const float*)d_in[1];
    const float* Wq = (const float*)d_in[2];
    const float* bq = (const float*)d_in[3];
    const float* Wk = (const float*)d_in[4];
    const float* bk = (const float*)d_in[5];
    const float* Wv = (const float*)d_in[6];
    const float* bv = (const float*)d_in[7];
    const float* Wo = (const float*)d_in[8];
    const float* bo = (const float*)d_in[9];

    float* out = (float*)d_out;
    float* res = out + (size_t)MTOT * KDIM;

    static int attr_set = 0;
    if (!attr_set) {
        cudaFuncSetAttribute(gemm_tc<0>, cudaFuncAttributeMaxDynamicSharedMemorySize, 55296);
        cudaFuncSetAttribute(gemm_tc<1>, cudaFuncAttributeMaxDynamicSharedMemorySize, 55296);
        cudaFuncSetAttribute(attn_tc,    cudaFuncAttributeMaxDynamicSharedMemorySize, 69632);
        attr_set = 1;
    }

    unsigned *p_qt, *p_ct, *p_wq, *p_wk, *p_wv, *p_wo, *p_k, *p_v, *p_multi;
    cudaGetSymbolAddress((void**)&p_qt, g_qt);
    cudaGetSymbolAddress((void**)&p_ct, g_ct);
    cudaGetSymbolAddress((void**)&p_wq, g_wq);
    cudaGetSymbolAddress((void**)&p_wk, g_wk);
    cudaGetSymbolAddress((void**)&p_wv, g_wv);
    cudaGetSymbolAddress((void**)&p_wo, g_wo);
    cudaGetSymbolAddress((void**)&p_k,  g_k);
    cudaGetSymbolAddress((void**)&p_v,  g_v);
    cudaGetSymbolAddress((void**)&p_multi, g_multi);

    // 1) round inputs + weights to tf32
    cvt_pre<<<12288, 256>>>(queries, context, Wq, Wk, Wv, Wo);

    // 2) Q projection -> residual (exact fp32; also Q source for attention)
    gemm_tc<0><<<dim3(16,32), 256, 55296>>>(p_qt, p_wq, p_wq, bq, bq,
                                            res, res, HDIM, KDIM*HDIM);
    // 3) K+V projections (fused grid) -> g_k/g_v, tf32-rounded
    gemm_tc<1><<<dim3(32,32), 256, 55296>>>(p_ct, p_wk, p_wv, bk, bv,
                                            p_k, p_v, HDIM, KDIM*HDIM);
    // 4) attention -> g_multi (tf32-rounded)
    attn_tc<<<dim3(8,64), 256, 69632>>>(res);
    // 5) output projection -> out (exact fp32 + bias)
    gemm_tc<0><<<dim3(16,32), 256, 55296>>>(p_multi, p_wo, p_wo, bo, bo,
                                            out, out, KDIM, HDIM);
}